// round 7
// baseline (speedup 1.0000x reference)
#include <cuda_runtime.h>
#include <cuda_bf16.h>
#include <cstdint>

#define BATCH 32
#define HID   256
#define VOCAB 10000
#define STEPS 256

// ---------------- recurrence config ----------------
#define CLUSTER 4          // CTAs per cluster (weights split across cluster)
#define BPC     2          // batch elements per cluster
#define DPC     64         // output dims per CTA
#define RTH     256        // threads: (kh, b, d) = 2 x 2 x 64

// ---------------- scratch (device globals: allocation-free) ----------------
__device__ __nv_bfloat16 g_Ahi[STEPS * BATCH * HID];   // hidden states, bf16 hi
__device__ __nv_bfloat16 g_Alo[STEPS * BATCH * HID];   // bf16 lo (residual)
__device__ __nv_bfloat16 g_Bhi[HID * VOCAB];           // W_hq split
__device__ __nv_bfloat16 g_Blo[HID * VOCAB];

__global__ void convB_kernel(const float* __restrict__ W) {
    int i = blockIdx.x * 256 + threadIdx.x;
    if (i < HID * VOCAB) {
        float v = W[i];
        __nv_bfloat16 h = __float2bfloat16(v);
        g_Bhi[i] = h;
        g_Blo[i] = __float2bfloat16(v - __bfloat162float(h));
    }
}

__device__ __forceinline__ uint32_t sptr(const void* p) {
    return (uint32_t)__cvta_generic_to_shared(p);
}

#define FMA2(acc, a, b) \
    asm("fma.rn.f32x2 %0, %1, %2, %0;" : "+l"(acc) : "l"(a), "l"(b))

__device__ __forceinline__ float2 unpack2(unsigned long long v) {
    float2 f;
    asm("mov.b64 {%0, %1}, %2;" : "=f"(f.x), "=f"(f.y) : "l"(v));
    return f;
}

__device__ __forceinline__ void st_cluster_f32(uint32_t laddr, int rank, float v) {
    uint32_t ra;
    asm("mapa.shared::cluster.u32 %0, %1, %2;" : "=r"(ra) : "r"(laddr), "r"(rank));
    asm volatile("st.shared::cluster.f32 [%0], %1;" :: "r"(ra), "f"(v) : "memory");
}

#define CLUSTER_SYNC() do { \
    asm volatile("barrier.cluster.arrive.aligned;" ::: "memory"); \
    asm volatile("barrier.cluster.wait.aligned;"   ::: "memory"); \
} while (0)

// smem layout (dynamic): weight slices interleaved by d for conflict-free LDS.
// Wq[g][kq][d] = float4 of W_h*[4kq..4kq+3][dim0+d]
struct RSmem {
    float4 Wq[3][HID / 4][DPC];   // 196608 B
    float4 hq[BPC][HID / 4];      // full h vector per local batch
    float4 rhq[BPC][HID / 4];     // full r*h vector per local batch
};

// ================= Phase A: clustered GRU recurrence =================
extern __shared__ __align__(16) char rsmem_raw[];

__global__ __launch_bounds__(RTH, 1) __cluster_dims__(CLUSTER, 1, 1)
void rnn_kernel(const int* __restrict__ X, const float* __restrict__ H0,
                const float* __restrict__ Wxz, const float* __restrict__ Whz, const float* __restrict__ bz,
                const float* __restrict__ Wxr, const float* __restrict__ Whr, const float* __restrict__ br,
                const float* __restrict__ Wxh, const float* __restrict__ Whh, const float* __restrict__ bh,
                float* __restrict__ outF)
{
    RSmem* s = reinterpret_cast<RSmem*>(rsmem_raw);
    const int tid  = threadIdx.x;
    const int rank = (int)(blockIdx.x & (CLUSTER - 1));
    const int cid  = (int)(blockIdx.x >> 2);
    const int dim0 = rank * DPC;
    const int kh   = tid & 1;            // k-half (0: kq 0..31, 1: kq 32..63)
    const int b    = (tid >> 1) & 1;     // local batch
    const int d    = tid >> 2;           // local dim
    const int bg   = cid * BPC + b;      // global batch
    const int dim  = dim0 + d;           // global dim owned by this thread
    const int kq0  = kh * (HID / 8);     // 32

    // ---- load weight slices (one-time), d-interleaved ----
    for (int i = tid; i < 3 * (HID / 4) * DPC; i += RTH) {
        int g  = i / ((HID / 4) * DPC);
        int r  = i % ((HID / 4) * DPC);
        int kq = r / DPC;
        int dd = r % DPC;
        const float* W = (g == 0) ? Whz : ((g == 1) ? Whr : Whh);
        float4 v;
        v.x = W[(kq * 4 + 0) * HID + dim0 + dd];
        v.y = W[(kq * 4 + 1) * HID + dim0 + dd];
        v.z = W[(kq * 4 + 2) * HID + dim0 + dd];
        v.w = W[(kq * 4 + 3) * HID + dim0 + dd];
        s->Wq[g][kq][dd] = v;
    }
    // ---- load initial h ----
    if (tid < BPC * (HID / 4)) {
        int bb = tid >> 6;
        int kq = tid & 63;
        s->hq[bb][kq] = *reinterpret_cast<const float4*>(&H0[(cid * BPC + bb) * HID + kq * 4]);
    }
    const float bzv = bz[dim];
    const float brv = br[dim];
    const float bhv = bh[dim];
    __syncthreads();
    CLUSTER_SYNC();

    const uint32_t rh_addr = sptr(&reinterpret_cast<float*>(s->rhq)[b * HID + dim]);
    const uint32_t h_addr  = sptr(&reinterpret_cast<float*>(s->hq)[b * HID + dim]);

    #pragma unroll 1
    for (int t = 0; t < STEPS; ++t) {
        // ---- gathers for this step (overlap with dot products) ----
        int   xv = X[bg * STEPS + t];
        float xz = Wxz[xv * HID + dim];
        float xr = Wxr[xv * HID + dim];
        float xh = Wxh[xv * HID + dim];
        float hold = reinterpret_cast<const float*>(s->hq)[b * HID + dim];

        // ---- phase A: z and r partial dots over this thread's k-half ----
        unsigned long long az0 = 0ull, az1 = 0ull, ar0 = 0ull, ar1 = 0ull;
        {
            const ulonglong2* wz = reinterpret_cast<const ulonglong2*>(&s->Wq[0][kq0][d]);
            const ulonglong2* wr = reinterpret_cast<const ulonglong2*>(&s->Wq[1][kq0][d]);
            const ulonglong2* hp = reinterpret_cast<const ulonglong2*>(&s->hq[b][kq0]);
            #pragma unroll 8
            for (int kq = 0; kq < HID / 8; ++kq) {
                ulonglong2 h2 = hp[kq];
                ulonglong2 a  = wz[kq * DPC];
                ulonglong2 c  = wr[kq * DPC];
                FMA2(az0, a.x, h2.x); FMA2(az1, a.y, h2.y);
                FMA2(ar0, c.x, h2.x); FMA2(ar1, c.y, h2.y);
            }
        }
        float2 z0 = unpack2(az0), z1 = unpack2(az1);
        float2 r0 = unpack2(ar0), r1 = unpack2(ar1);
        float zp = (z0.x + z0.y) + (z1.x + z1.y);
        float rp = (r0.x + r0.y) + (r1.x + r1.y);
        zp += __shfl_xor_sync(0xFFFFFFFFu, zp, 1);   // combine k-halves (partner lane)
        rp += __shfl_xor_sync(0xFFFFFFFFu, rp, 1);
        float zv = 1.f / (1.f + expf(-(zp + xz + bzv)));
        float rv = 1.f / (1.f + expf(-(rp + xr + brv)));
        float rh = rv * hold;

        // broadcast r*h slice to all cluster CTAs (kh==0 lanes only)
        if (kh == 0) {
            #pragma unroll
            for (int rr = 0; rr < CLUSTER; ++rr) st_cluster_f32(rh_addr, rr, rh);
        }
        CLUSTER_SYNC();

        // ---- phase B: h_tilda partial dot over this thread's k-half ----
        unsigned long long ah0 = 0ull, ah1 = 0ull;
        {
            const ulonglong2* wh = reinterpret_cast<const ulonglong2*>(&s->Wq[2][kq0][d]);
            const ulonglong2* rp2 = reinterpret_cast<const ulonglong2*>(&s->rhq[b][kq0]);
            #pragma unroll 8
            for (int kq = 0; kq < HID / 8; ++kq) {
                ulonglong2 r2 = rp2[kq];
                ulonglong2 a  = wh[kq * DPC];
                FMA2(ah0, a.x, r2.x); FMA2(ah1, a.y, r2.y);
            }
        }
        float2 h0 = unpack2(ah0), h1 = unpack2(ah1);
        float hp2 = (h0.x + h0.y) + (h1.x + h1.y);
        hp2 += __shfl_xor_sync(0xFFFFFFFFu, hp2, 1);
        float htl  = tanhf(hp2 + xh + bhv);
        float hnew = zv * hold + (1.f - zv) * htl;

        if (kh == 0) {
            #pragma unroll
            for (int rr = 0; rr < CLUSTER; ++rr) st_cluster_f32(h_addr, rr, hnew);
            int row = t * BATCH + bg;
            __nv_bfloat16 hb = __float2bfloat16(hnew);
            g_Ahi[row * HID + dim] = hb;
            g_Alo[row * HID + dim] = __float2bfloat16(hnew - __bfloat162float(hb));
            if (t == STEPS - 1) outF[bg * HID + dim] = hnew;
        }
        CLUSTER_SYNC();
    }
}

// ================= Phase B: output GEMM (split-bf16 tensor cores) =================
#define GBM 128
#define GBN 128
#define GBK 16
#define GNC (HID / GBK)
#define GTHREADS 256

#define CP16(dst, src, sz) \
    asm volatile("cp.async.cg.shared.global [%0], [%1], 16, %2;" :: "r"(dst), "l"(src), "r"(sz))
#define LDSM4(r, addr) \
    asm volatile("ldmatrix.sync.aligned.m8n8.x4.shared.b16 {%0,%1,%2,%3}, [%4];" \
        : "=r"((r)[0]), "=r"((r)[1]), "=r"((r)[2]), "=r"((r)[3]) : "r"(addr))
#define LDSMT2(r, addr) \
    asm volatile("ldmatrix.sync.aligned.m8n8.x2.trans.shared.b16 {%0,%1}, [%2];" \
        : "=r"((r)[0]), "=r"((r)[1]) : "r"(addr))
#define MMA16816(d, a, b) \
    asm volatile("mma.sync.aligned.m16n8k16.row.col.f32.bf16.bf16.f32 " \
        "{%0,%1,%2,%3}, {%4,%5,%6,%7}, {%8,%9}, {%0,%1,%2,%3};" \
        : "+f"((d)[0]), "+f"((d)[1]), "+f"((d)[2]), "+f"((d)[3]) \
        : "r"((a)[0]), "r"((a)[1]), "r"((a)[2]), "r"((a)[3]), "r"((b)[0]), "r"((b)[1]))

__global__ __launch_bounds__(GTHREADS, 2)
void out_gemm(const float* __restrict__ bias, float* __restrict__ C)
{
    __shared__ __align__(16) __nv_bfloat16 sAh[2][GBM * GBK];
    __shared__ __align__(16) __nv_bfloat16 sAl[2][GBM * GBK];
    __shared__ __align__(16) __nv_bfloat16 sBh[2][GBK * GBN];
    __shared__ __align__(16) __nv_bfloat16 sBl[2][GBK * GBN];

    const int tid  = threadIdx.x;
    const int lane = tid & 31;
    const int warp = tid >> 5;
    const int wm   = (warp >> 2) * 64;
    const int wn   = (warp & 3) * 32;
    const int m0   = blockIdx.y * GBM;
    const int n0   = blockIdx.x * GBN;

    float acc[4][4][4];
    #pragma unroll
    for (int i = 0; i < 4; ++i)
        #pragma unroll
        for (int j = 0; j < 4; ++j)
            #pragma unroll
            for (int q = 0; q < 4; ++q) acc[i][j][q] = 0.f;

    auto load_stage = [&](int st, int k0) {
        #pragma unroll
        for (int i = 0; i < 2; ++i) {
            int idx = tid + (i << 8);
            int sel = idx >> 8;
            int r   = idx & 255;
            int m   = r >> 1;
            int ku  = r & 1;
            const __nv_bfloat16* g = (sel ? g_Alo : g_Ahi) + (size_t)(m0 + m) * HID + k0 + ku * 8;
            uint32_t d = sptr(sel ? sAl[st] : sAh[st]) + m * 32 + ((ku ^ ((m >> 2) & 1)) << 4);
            CP16(d, g, 16);
        }
        #pragma unroll
        for (int i = 0; i < 2; ++i) {
            int idx = tid + (i << 8);
            int sel = idx >> 8;
            int r   = idx & 255;
            int k   = r >> 4;
            int nu  = r & 15;
            int col = n0 + nu * 8;
            const __nv_bfloat16* g = (sel ? g_Blo : g_Bhi) + (size_t)(k0 + k) * VOCAB + col;
            uint32_t d = sptr(sel ? sBl[st] : sBh[st]) + k * 256 + ((nu ^ (k & 7)) << 4);
            int sz = (col + 8 <= VOCAB) ? 16 : 0;
            CP16(d, g, sz);
        }
    };

    load_stage(0, 0);
    asm volatile("cp.async.commit_group;");

    const int lrow = lane & 15;
    const int lkb  = (lane >> 4) & 1;

    #pragma unroll 1
    for (int c = 0; c < GNC; ++c) {
        if (c + 1 < GNC) load_stage((c + 1) & 1, (c + 1) * GBK);
        asm volatile("cp.async.commit_group;");
        asm volatile("cp.async.wait_group 1;");
        __syncthreads();

        const int st = c & 1;
        uint32_t ah[4][4], al[4][4], bh[4][2], bl[4][2];
        #pragma unroll
        for (int mt = 0; mt < 4; ++mt) {
            int m = wm + mt * 16 + lrow;
            uint32_t off = m * 32 + ((lkb ^ ((m >> 2) & 1)) << 4);
            LDSM4(ah[mt], sptr(sAh[st]) + off);
            LDSM4(al[mt], sptr(sAl[st]) + off);
        }
        #pragma unroll
        for (int nt = 0; nt < 4; ++nt) {
            int k = lrow;
            int n = wn + nt * 8;
            uint32_t off = k * 256 + (((n >> 3) ^ (k & 7)) << 4);
            LDSMT2(bh[nt], sptr(sBh[st]) + off);
            LDSMT2(bl[nt], sptr(sBl[st]) + off);
        }
        #pragma unroll
        for (int mt = 0; mt < 4; ++mt)
            #pragma unroll
            for (int nt = 0; nt < 4; ++nt) {
                MMA16816(acc[mt][nt], ah[mt], bh[nt]);
                MMA16816(acc[mt][nt], ah[mt], bl[nt]);
                MMA16816(acc[mt][nt], al[mt], bh[nt]);
            }
        __syncthreads();
    }

    #pragma unroll
    for (int nt = 0; nt < 4; ++nt) {
        int cbase = n0 + wn + nt * 8 + 2 * (lane & 3);
        float2 bv = make_float2(0.f, 0.f);
        if (cbase + 1 < VOCAB) bv = *reinterpret_cast<const float2*>(bias + cbase);
        #pragma unroll
        for (int mt = 0; mt < 4; ++mt) {
            int r0 = m0 + wm + mt * 16 + (lane >> 2);
            if (cbase + 1 < VOCAB) {
                float2 v0 = make_float2(acc[mt][nt][0] + bv.x, acc[mt][nt][1] + bv.y);
                float2 v1 = make_float2(acc[mt][nt][2] + bv.x, acc[mt][nt][3] + bv.y);
                *reinterpret_cast<float2*>(C + (size_t)r0 * VOCAB + cbase) = v0;
                *reinterpret_cast<float2*>(C + (size_t)(r0 + 8) * VOCAB + cbase) = v1;
            }
        }
    }
}

// ================= launch =================
extern "C" void kernel_launch(void* const* d_in, const int* in_sizes, int n_in,
                              void* d_out, int out_size) {
    const int*   X   = (const int*)  d_in[0];
    const float* H0  = (const float*)d_in[1];
    const float* Wxz = (const float*)d_in[2];
    const float* Whz = (const float*)d_in[3];
    const float* bz  = (const float*)d_in[4];
    const float* Wxr = (const float*)d_in[5];
    const float* Whr = (const float*)d_in[6];
    const float* br  = (const float*)d_in[7];
    const float* Wxh = (const float*)d_in[8];
    const float* Whh = (const float*)d_in[9];
    const float* bh  = (const float*)d_in[10];
    const float* Whq = (const float*)d_in[11];
    const float* bq  = (const float*)d_in[12];

    float* out  = (float*)d_out;
    float* outF = out + (out_size - BATCH * HID);

    static bool attr_set = false;
    if (!attr_set) {
        cudaFuncSetAttribute(rnn_kernel, cudaFuncAttributeMaxDynamicSharedMemorySize,
                             (int)sizeof(RSmem));
        attr_set = true;
    }

    convB_kernel<<<(HID * VOCAB + 255) / 256, 256>>>(Whq);
    rnn_kernel<<<(BATCH / BPC) * CLUSTER, RTH, sizeof(RSmem)>>>(
        X, H0, Wxz, Whz, bz, Wxr, Whr, br, Wxh, Whh, bh, outF);
    out_gemm<<<dim3((VOCAB + GBN - 1) / GBN, (STEPS * BATCH) / GBM), GTHREADS>>>(bq, out);
}

// round 8
// speedup vs baseline: 1.0386x; 1.0386x over previous
#include <cuda_runtime.h>
#include <cuda_bf16.h>
#include <cstdint>

#define BATCH 32
#define HID   256
#define VOCAB 10000
#define STEPS 256

// ---------------- recurrence config ----------------
#define CLUSTER 4          // CTAs per cluster (weights split across cluster)
#define BPC     2          // batch elements per cluster
#define DPC     64         // output dims per CTA
#define RTH     256        // threads: (kh, b, d) = 2 x 2 x 64
#define KQH     (HID / 8)  // 32 kq iterations per k-half

// ---------------- scratch (device globals: allocation-free) ----------------
__device__ __nv_bfloat16 g_Ahi[STEPS * BATCH * HID];   // hidden states, bf16 hi
__device__ __nv_bfloat16 g_Alo[STEPS * BATCH * HID];   // bf16 lo (residual)
__device__ __nv_bfloat16 g_Bhi[HID * VOCAB];           // W_hq split
__device__ __nv_bfloat16 g_Blo[HID * VOCAB];

__global__ void convB_kernel(const float* __restrict__ W) {
    int i = blockIdx.x * 256 + threadIdx.x;
    if (i < HID * VOCAB) {
        float v = W[i];
        __nv_bfloat16 h = __float2bfloat16(v);
        g_Bhi[i] = h;
        g_Blo[i] = __float2bfloat16(v - __bfloat162float(h));
    }
}

__device__ __forceinline__ uint32_t sptr(const void* p) {
    return (uint32_t)__cvta_generic_to_shared(p);
}

#define FMA2(acc, a, b) \
    asm("fma.rn.f32x2 %0, %1, %2, %0;" : "+l"(acc) : "l"(a), "l"(b))

__device__ __forceinline__ float2 unpack2(unsigned long long v) {
    float2 f;
    asm("mov.b64 {%0, %1}, %2;" : "=f"(f.x), "=f"(f.y) : "l"(v));
    return f;
}

__device__ __forceinline__ void st_cluster_f32(uint32_t laddr, int rank, float v) {
    uint32_t ra;
    asm("mapa.shared::cluster.u32 %0, %1, %2;" : "=r"(ra) : "r"(laddr), "r"(rank));
    asm volatile("st.shared::cluster.f32 [%0], %1;" :: "r"(ra), "f"(v) : "memory");
}

#define CLUSTER_SYNC() do { \
    asm volatile("barrier.cluster.arrive.aligned;" ::: "memory"); \
    asm volatile("barrier.cluster.wait.aligned;"   ::: "memory"); \
} while (0)

// smem weight layout: k-half INNERMOST so partner lanes (kh=0/1, same d) read
// ADJACENT 16B chunks -> warp covers 256 consecutive bytes -> conflict-free.
// Wq[g][kq][d][kh] = float4 of W_h*[ (kh*128 + kq*4) .. +3 ][dim0+d]
struct RSmem {
    float4 Wq[3][KQH][DPC][2];    // 196608 B (same size as before)
    float4 hq[BPC][HID / 4];      // full h vector per local batch
    float4 rhq[BPC][HID / 4];     // full r*h vector per local batch
};

// ================= Phase A: clustered GRU recurrence =================
extern __shared__ __align__(16) char rsmem_raw[];

__global__ __launch_bounds__(RTH, 1) __cluster_dims__(CLUSTER, 1, 1)
void rnn_kernel(const int* __restrict__ X, const float* __restrict__ H0,
                const float* __restrict__ Wxz, const float* __restrict__ Whz, const float* __restrict__ bz,
                const float* __restrict__ Wxr, const float* __restrict__ Whr, const float* __restrict__ br,
                const float* __restrict__ Wxh, const float* __restrict__ Whh, const float* __restrict__ bh,
                float* __restrict__ outF)
{
    RSmem* s = reinterpret_cast<RSmem*>(rsmem_raw);
    const int tid  = threadIdx.x;
    const int rank = (int)(blockIdx.x & (CLUSTER - 1));
    const int cid  = (int)(blockIdx.x >> 2);
    const int dim0 = rank * DPC;
    const int kh   = tid & 1;            // k-half (0: k 0..127, 1: k 128..255)
    const int b    = (tid >> 1) & 1;     // local batch
    const int d    = tid >> 2;           // local dim
    const int bg   = cid * BPC + b;      // global batch
    const int dim  = dim0 + d;           // global dim owned by this thread

    // ---- load weight slices (one-time), [g][kq][d][kh] layout ----
    for (int i = tid; i < 3 * KQH * DPC * 2; i += RTH) {
        int g   = i / (KQH * DPC * 2);
        int r   = i % (KQH * DPC * 2);
        int kq  = r / (DPC * 2);
        int r2  = r % (DPC * 2);
        int dd  = r2 >> 1;
        int kk  = r2 & 1;
        const float* W = (g == 0) ? Whz : ((g == 1) ? Whr : Whh);
        int kbase = kk * (HID / 2) + kq * 4;
        float4 v;
        v.x = W[(kbase + 0) * HID + dim0 + dd];
        v.y = W[(kbase + 1) * HID + dim0 + dd];
        v.z = W[(kbase + 2) * HID + dim0 + dd];
        v.w = W[(kbase + 3) * HID + dim0 + dd];
        s->Wq[g][kq][dd][kk] = v;
    }
    // ---- load initial h ----
    if (tid < BPC * (HID / 4)) {
        int bb = tid >> 6;
        int kq = tid & 63;
        s->hq[bb][kq] = *reinterpret_cast<const float4*>(&H0[(cid * BPC + bb) * HID + kq * 4]);
    }
    const float bzv = bz[dim];
    const float brv = br[dim];
    const float bhv = bh[dim];
    __syncthreads();
    CLUSTER_SYNC();

    const uint32_t rh_addr = sptr(&reinterpret_cast<float*>(s->rhq)[b * HID + dim]);
    const uint32_t h_addr  = sptr(&reinterpret_cast<float*>(s->hq)[b * HID + dim]);
    const int hq0 = kh * KQH;   // this thread's k-half offset into hq/rhq (float4 units)

    #pragma unroll 1
    for (int t = 0; t < STEPS; ++t) {
        // ---- gathers for this step (overlap with dot products) ----
        int   xv = X[bg * STEPS + t];
        float xz = Wxz[xv * HID + dim];
        float xr = Wxr[xv * HID + dim];
        float xh = Wxh[xv * HID + dim];
        float hold = reinterpret_cast<const float*>(s->hq)[b * HID + dim];

        // ---- phase A: z and r partial dots over this thread's k-half ----
        unsigned long long az0 = 0ull, az1 = 0ull, ar0 = 0ull, ar1 = 0ull;
        {
            const ulonglong2* wz = reinterpret_cast<const ulonglong2*>(&s->Wq[0][0][d][kh]);
            const ulonglong2* wr = reinterpret_cast<const ulonglong2*>(&s->Wq[1][0][d][kh]);
            const ulonglong2* hp = reinterpret_cast<const ulonglong2*>(&s->hq[b][hq0]);
            #pragma unroll 8
            for (int kq = 0; kq < KQH; ++kq) {
                ulonglong2 h2 = hp[kq];
                ulonglong2 a  = wz[kq * (DPC * 2)];
                ulonglong2 c  = wr[kq * (DPC * 2)];
                FMA2(az0, a.x, h2.x); FMA2(az1, a.y, h2.y);
                FMA2(ar0, c.x, h2.x); FMA2(ar1, c.y, h2.y);
            }
        }
        float2 z0 = unpack2(az0), z1 = unpack2(az1);
        float2 r0 = unpack2(ar0), r1 = unpack2(ar1);
        float zp = (z0.x + z0.y) + (z1.x + z1.y);
        float rp = (r0.x + r0.y) + (r1.x + r1.y);
        zp += __shfl_xor_sync(0xFFFFFFFFu, zp, 1);   // combine k-halves (adjacent lane)
        rp += __shfl_xor_sync(0xFFFFFFFFu, rp, 1);
        float zv = 1.f / (1.f + expf(-(zp + xz + bzv)));
        float rv = 1.f / (1.f + expf(-(rp + xr + brv)));
        float rh = rv * hold;

        // broadcast r*h slice to all cluster CTAs (kh==0 lanes only)
        if (kh == 0) {
            #pragma unroll
            for (int rr = 0; rr < CLUSTER; ++rr) st_cluster_f32(rh_addr, rr, rh);
        }
        CLUSTER_SYNC();

        // ---- phase B: h_tilda partial dot over this thread's k-half ----
        unsigned long long ah0 = 0ull, ah1 = 0ull;
        {
            const ulonglong2* wh  = reinterpret_cast<const ulonglong2*>(&s->Wq[2][0][d][kh]);
            const ulonglong2* rp2 = reinterpret_cast<const ulonglong2*>(&s->rhq[b][hq0]);
            #pragma unroll 8
            for (int kq = 0; kq < KQH; ++kq) {
                ulonglong2 r2 = rp2[kq];
                ulonglong2 a  = wh[kq * (DPC * 2)];
                FMA2(ah0, a.x, r2.x); FMA2(ah1, a.y, r2.y);
            }
        }
        float2 h0 = unpack2(ah0), h1 = unpack2(ah1);
        float hp2 = (h0.x + h0.y) + (h1.x + h1.y);
        hp2 += __shfl_xor_sync(0xFFFFFFFFu, hp2, 1);
        float htl  = tanhf(hp2 + xh + bhv);
        float hnew = zv * hold + (1.f - zv) * htl;

        if (kh == 0) {
            #pragma unroll
            for (int rr = 0; rr < CLUSTER; ++rr) st_cluster_f32(h_addr, rr, hnew);
            int row = t * BATCH + bg;
            __nv_bfloat16 hb = __float2bfloat16(hnew);
            g_Ahi[row * HID + dim] = hb;
            g_Alo[row * HID + dim] = __float2bfloat16(hnew - __bfloat162float(hb));
            if (t == STEPS - 1) outF[bg * HID + dim] = hnew;
        }
        CLUSTER_SYNC();
    }
}

// ================= Phase B: output GEMM (split-bf16 tensor cores) =================
// (byte-identical to round-3/6 passing version)
#define GBM 128
#define GBN 128
#define GBK 16
#define GNC (HID / GBK)
#define GTHREADS 256

#define CP16(dst, src, sz) \
    asm volatile("cp.async.cg.shared.global [%0], [%1], 16, %2;" :: "r"(dst), "l"(src), "r"(sz))
#define LDSM4(r, addr) \
    asm volatile("ldmatrix.sync.aligned.m8n8.x4.shared.b16 {%0,%1,%2,%3}, [%4];" \
        : "=r"((r)[0]), "=r"((r)[1]), "=r"((r)[2]), "=r"((r)[3]) : "r"(addr))
#define LDSMT2(r, addr) \
    asm volatile("ldmatrix.sync.aligned.m8n8.x2.trans.shared.b16 {%0,%1}, [%2];" \
        : "=r"((r)[0]), "=r"((r)[1]) : "r"(addr))
#define MMA16816(d, a, b) \
    asm volatile("mma.sync.aligned.m16n8k16.row.col.f32.bf16.bf16.f32 " \
        "{%0,%1,%2,%3}, {%4,%5,%6,%7}, {%8,%9}, {%0,%1,%2,%3};" \
        : "+f"((d)[0]), "+f"((d)[1]), "+f"((d)[2]), "+f"((d)[3]) \
        : "r"((a)[0]), "r"((a)[1]), "r"((a)[2]), "r"((a)[3]), "r"((b)[0]), "r"((b)[1]))

__global__ __launch_bounds__(GTHREADS, 1)
void out_gemm(const float* __restrict__ bias, float* __restrict__ C)
{
    __shared__ __align__(16) __nv_bfloat16 sAh[2][GBM * GBK];
    __shared__ __align__(16) __nv_bfloat16 sAl[2][GBM * GBK];
    __shared__ __align__(16) __nv_bfloat16 sBh[2][GBK * GBN];
    __shared__ __align__(16) __nv_bfloat16 sBl[2][GBK * GBN];

    const int tid  = threadIdx.x;
    const int lane = tid & 31;
    const int warp = tid >> 5;
    const int wm   = (warp >> 2) * 64;
    const int wn   = (warp & 3) * 32;
    const int m0   = blockIdx.y * GBM;
    const int n0   = blockIdx.x * GBN;

    float acc[4][4][4];
    #pragma unroll
    for (int i = 0; i < 4; ++i)
        #pragma unroll
        for (int j = 0; j < 4; ++j)
            #pragma unroll
            for (int q = 0; q < 4; ++q) acc[i][j][q] = 0.f;

    auto load_stage = [&](int st, int k0) {
        #pragma unroll
        for (int i = 0; i < 2; ++i) {
            int idx = tid + (i << 8);
            int sel = idx >> 8;
            int r   = idx & 255;
            int m   = r >> 1;
            int ku  = r & 1;
            const __nv_bfloat16* g = (sel ? g_Alo : g_Ahi) + (size_t)(m0 + m) * HID + k0 + ku * 8;
            uint32_t d = sptr(sel ? sAl[st] : sAh[st]) + m * 32 + ((ku ^ ((m >> 2) & 1)) << 4);
            CP16(d, g, 16);
        }
        #pragma unroll
        for (int i = 0; i < 2; ++i) {
            int idx = tid + (i << 8);
            int sel = idx >> 8;
            int r   = idx & 255;
            int k   = r >> 4;
            int nu  = r & 15;
            int col = n0 + nu * 8;
            const __nv_bfloat16* g = (sel ? g_Blo : g_Bhi) + (size_t)(k0 + k) * VOCAB + col;
            uint32_t d = sptr(sel ? sBl[st] : sBh[st]) + k * 256 + ((nu ^ (k & 7)) << 4);
            int sz = (col + 8 <= VOCAB) ? 16 : 0;
            CP16(d, g, sz);
        }
    };

    load_stage(0, 0);
    asm volatile("cp.async.commit_group;");

    const int lrow = lane & 15;
    const int lkb  = (lane >> 4) & 1;

    #pragma unroll 1
    for (int c = 0; c < GNC; ++c) {
        if (c + 1 < GNC) load_stage((c + 1) & 1, (c + 1) * GBK);
        asm volatile("cp.async.commit_group;");
        asm volatile("cp.async.wait_group 1;");
        __syncthreads();

        const int st = c & 1;
        uint32_t ah[4][4], al[4][4], bh[4][2], bl[4][2];
        #pragma unroll
        for (int mt = 0; mt < 4; ++mt) {
            int m = wm + mt * 16 + lrow;
            uint32_t off = m * 32 + ((lkb ^ ((m >> 2) & 1)) << 4);
            LDSM4(ah[mt], sptr(sAh[st]) + off);
            LDSM4(al[mt], sptr(sAl[st]) + off);
        }
        #pragma unroll
        for (int nt = 0; nt < 4; ++nt) {
            int k = lrow;
            int n = wn + nt * 8;
            uint32_t off = k * 256 + (((n >> 3) ^ (k & 7)) << 4);
            LDSMT2(bh[nt], sptr(sBh[st]) + off);
            LDSMT2(bl[nt], sptr(sBl[st]) + off);
        }
        #pragma unroll
        for (int mt = 0; mt < 4; ++mt)
            #pragma unroll
            for (int nt = 0; nt < 4; ++nt) {
                MMA16816(acc[mt][nt], ah[mt], bh[nt]);
                MMA16816(acc[mt][nt], ah[mt], bl[nt]);
                MMA16816(acc[mt][nt], al[mt], bh[nt]);
            }
        __syncthreads();
    }

    #pragma unroll
    for (int nt = 0; nt < 4; ++nt) {
        int cbase = n0 + wn + nt * 8 + 2 * (lane & 3);
        float2 bv = make_float2(0.f, 0.f);
        if (cbase + 1 < VOCAB) bv = *reinterpret_cast<const float2*>(bias + cbase);
        #pragma unroll
        for (int mt = 0; mt < 4; ++mt) {
            int r0 = m0 + wm + mt * 16 + (lane >> 2);
            if (cbase + 1 < VOCAB) {
                float2 v0 = make_float2(acc[mt][nt][0] + bv.x, acc[mt][nt][1] + bv.y);
                float2 v1 = make_float2(acc[mt][nt][2] + bv.x, acc[mt][nt][3] + bv.y);
                *reinterpret_cast<float2*>(C + (size_t)r0 * VOCAB + cbase) = v0;
                *reinterpret_cast<float2*>(C + (size_t)(r0 + 8) * VOCAB + cbase) = v1;
            }
        }
    }
}

// ================= launch =================
extern "C" void kernel_launch(void* const* d_in, const int* in_sizes, int n_in,
                              void* d_out, int out_size) {
    const int*   X   = (const int*)  d_in[0];
    const float* H0  = (const float*)d_in[1];
    const float* Wxz = (const float*)d_in[2];
    const float* Whz = (const float*)d_in[3];
    const float* bz  = (const float*)d_in[4];
    const float* Wxr = (const float*)d_in[5];
    const float* Whr = (const float*)d_in[6];
    const float* br  = (const float*)d_in[7];
    const float* Wxh = (const float*)d_in[8];
    const float* Whh = (const float*)d_in[9];
    const float* bh  = (const float*)d_in[10];
    const float* Whq = (const float*)d_in[11];
    const float* bq  = (const float*)d_in[12];

    float* out  = (float*)d_out;
    float* outF = out + (out_size - BATCH * HID);

    static bool attr_set = false;
    if (!attr_set) {
        cudaFuncSetAttribute(rnn_kernel, cudaFuncAttributeMaxDynamicSharedMemorySize,
                             (int)sizeof(RSmem));
        attr_set = true;
    }

    convB_kernel<<<(HID * VOCAB + 255) / 256, 256>>>(Whq);
    rnn_kernel<<<(BATCH / BPC) * CLUSTER, RTH, sizeof(RSmem)>>>(
        X, H0, Wxz, Whz, bz, Wxr, Whr, br, Wxh, Whh, bh, outF);
    out_gemm<<<dim3((VOCAB + GBN - 1) / GBN, (STEPS * BATCH) / GBM), GTHREADS>>>(bq, out);
}

// round 9
// speedup vs baseline: 1.6960x; 1.6329x over previous
#include <cuda_runtime.h>
#include <cuda_bf16.h>
#include <cstdint>

#define BATCH 32
#define HID   256
#define VOCAB 10000
#define STEPS 256

// ---------------- config ----------------
#define CLUSTER 4
#define BPC     2
#define DPC     64
#define NREC    64                 // recurrence CTAs (bids 0..63, wave 1)
#define FTH     256                // threads per CTA (fused kernel)

#define GBM 128
#define GBN 128
#define GBK 16
#define GNC (HID / GBK)
#define NTN ((VOCAB + GBN - 1) / GBN)   // 79 N tiles
#define NTM ((STEPS * BATCH) / GBM)     // 64 M tiles

// ---------------- scratch (device globals: allocation-free) ----------------
__device__ __nv_bfloat16 g_Ahi[STEPS * BATCH * HID];
__device__ __nv_bfloat16 g_Alo[STEPS * BATCH * HID];
__device__ __nv_bfloat16 g_Bhi[HID * VOCAB];
__device__ __nv_bfloat16 g_Blo[HID * VOCAB];
__device__ unsigned g_prog[NREC];   // per-recurrence-CTA step progress (t+1)

__global__ void prog_reset_kernel() {
    if (threadIdx.x < NREC) g_prog[threadIdx.x] = 0u;
}

__global__ void convB_kernel(const float* __restrict__ W) {
    int i = blockIdx.x * 256 + threadIdx.x;
    if (i < HID * VOCAB) {
        float v = W[i];
        __nv_bfloat16 h = __float2bfloat16(v);
        g_Bhi[i] = h;
        g_Blo[i] = __float2bfloat16(v - __bfloat162float(h));
    }
}

__device__ __forceinline__ uint32_t sptr(const void* p) {
    return (uint32_t)__cvta_generic_to_shared(p);
}
__device__ __forceinline__ unsigned ld_acq(const unsigned* p) {
    unsigned v;
    asm volatile("ld.acquire.gpu.global.u32 %0, [%1];" : "=r"(v) : "l"(p) : "memory");
    return v;
}
__device__ __forceinline__ void st_rel(unsigned* p, unsigned v) {
    asm volatile("st.release.gpu.global.u32 [%0], %1;" :: "l"(p), "r"(v) : "memory");
}

#define FMA2(acc, a, b) \
    asm("fma.rn.f32x2 %0, %1, %2, %0;" : "+l"(acc) : "l"(a), "l"(b))

__device__ __forceinline__ float2 unpack2(unsigned long long v) {
    float2 f;
    asm("mov.b64 {%0, %1}, %2;" : "=f"(f.x), "=f"(f.y) : "l"(v));
    return f;
}

__device__ __forceinline__ void st_cluster_f32(uint32_t laddr, int rank, float v) {
    uint32_t ra;
    asm("mapa.shared::cluster.u32 %0, %1, %2;" : "=r"(ra) : "r"(laddr), "r"(rank));
    asm volatile("st.shared::cluster.f32 [%0], %1;" :: "r"(ra), "f"(v) : "memory");
}

#define CLUSTER_SYNC() do { \
    asm volatile("barrier.cluster.arrive.aligned;" ::: "memory"); \
    asm volatile("barrier.cluster.wait.aligned;"   ::: "memory"); \
} while (0)

// ---------------- smem overlays (one dynamic buffer) ----------------
struct RSmem {                           // recurrence CTAs (R6-exact layout)
    float4 Wq[3][HID / 4][DPC];          // 196608 B
    float4 hq[BPC][HID / 4];
    float4 rhq[BPC][HID / 4];
};
struct GSmem {                           // GEMM CTAs (32 KB region of same buffer)
    __nv_bfloat16 Ah[2][GBM * GBK];
    __nv_bfloat16 Al[2][GBM * GBK];
    __nv_bfloat16 Bh[2][GBK * GBN];
    __nv_bfloat16 Bl[2][GBK * GBN];
};

extern __shared__ __align__(16) char dyn_smem[];

// ================= recurrence body (R6-exact, tid<128 active) =================
__device__ void rnn_body(const int* __restrict__ X, const float* __restrict__ H0,
                         const float* __restrict__ Wxz, const float* __restrict__ Whz, const float* __restrict__ bz,
                         const float* __restrict__ Wxr, const float* __restrict__ Whr, const float* __restrict__ br,
                         const float* __restrict__ Wxh, const float* __restrict__ Whh, const float* __restrict__ bh,
                         float* __restrict__ outF)
{
    RSmem* s = reinterpret_cast<RSmem*>(dyn_smem);
    const int tid    = threadIdx.x;
    const bool active = tid < 128;
    const int rank = (int)(blockIdx.x & (CLUSTER - 1));
    const int cid  = (int)(blockIdx.x >> 2);
    const int dim0 = rank * DPC;
    const int b    = tid & 1;
    const int d    = active ? (tid >> 1) : 0;
    const int bg   = cid * BPC + b;
    const int dim  = dim0 + d;

    // one-time weight slice load (all 256 threads help)
    for (int i = tid; i < 3 * (HID / 4) * DPC; i += FTH) {
        int g  = i / ((HID / 4) * DPC);
        int r  = i % ((HID / 4) * DPC);
        int kq = r / DPC;
        int dd = r % DPC;
        const float* W = (g == 0) ? Whz : ((g == 1) ? Whr : Whh);
        float4 v;
        v.x = W[(kq * 4 + 0) * HID + dim0 + dd];
        v.y = W[(kq * 4 + 1) * HID + dim0 + dd];
        v.z = W[(kq * 4 + 2) * HID + dim0 + dd];
        v.w = W[(kq * 4 + 3) * HID + dim0 + dd];
        s->Wq[g][kq][dd] = v;
    }
    if (tid < BPC * (HID / 4)) {
        int bb = tid >> 6;
        int kq = tid & 63;
        s->hq[bb][kq] = *reinterpret_cast<const float4*>(&H0[(cid * BPC + bb) * HID + kq * 4]);
    }
    const float bzv = bz[dim];
    const float brv = br[dim];
    const float bhv = bh[dim];
    __syncthreads();
    CLUSTER_SYNC();

    const uint32_t rh_addr = sptr(&reinterpret_cast<float*>(s->rhq)[b * HID + dim]);
    const uint32_t h_addr  = sptr(&reinterpret_cast<float*>(s->hq)[b * HID + dim]);

    #pragma unroll 1
    for (int t = 0; t < STEPS; ++t) {
        if (active) {
            int   xv = X[bg * STEPS + t];
            float xz = Wxz[xv * HID + dim];
            float xr = Wxr[xv * HID + dim];
            float hold = reinterpret_cast<const float*>(s->hq)[b * HID + dim];

            unsigned long long az0 = 0ull, az1 = 0ull, ar0 = 0ull, ar1 = 0ull;
            const ulonglong2* wz = reinterpret_cast<const ulonglong2*>(&s->Wq[0][0][d]);
            const ulonglong2* wr = reinterpret_cast<const ulonglong2*>(&s->Wq[1][0][d]);
            const ulonglong2* hp = reinterpret_cast<const ulonglong2*>(&s->hq[b][0]);
            #pragma unroll 16
            for (int kq = 0; kq < HID / 4; ++kq) {
                ulonglong2 h2 = hp[kq];
                ulonglong2 a  = wz[kq * DPC];
                ulonglong2 c  = wr[kq * DPC];
                FMA2(az0, a.x, h2.x); FMA2(az1, a.y, h2.y);
                FMA2(ar0, c.x, h2.x); FMA2(ar1, c.y, h2.y);
            }
            float2 z0 = unpack2(az0), z1 = unpack2(az1);
            float2 r0 = unpack2(ar0), r1 = unpack2(ar1);
            float zv = 1.f / (1.f + expf(-(((z0.x + z0.y) + (z1.x + z1.y)) + xz + bzv)));
            float rv = 1.f / (1.f + expf(-(((r0.x + r0.y) + (r1.x + r1.y)) + xr + brv)));
            float rh = rv * hold;
            #pragma unroll
            for (int rr = 0; rr < CLUSTER; ++rr) st_cluster_f32(rh_addr, rr, rh);
        }
        CLUSTER_SYNC();

        if (active) {
            int   xv = X[bg * STEPS + t];
            float xh = Wxh[xv * HID + dim];
            float hold = reinterpret_cast<const float*>(s->hq)[b * HID + dim];
            float zv;   // recompute z from nothing? no — keep in reg across barrier
            // NOTE: zv/hold survive in registers across CLUSTER_SYNC; recompute not needed.
            // (we fold phase-1 zv into a register below)
            (void)zv;

            unsigned long long ah0 = 0ull, ah1 = 0ull;
            const ulonglong2* wh = reinterpret_cast<const ulonglong2*>(&s->Wq[2][0][d]);
            const ulonglong2* rp = reinterpret_cast<const ulonglong2*>(&s->rhq[b][0]);
            #pragma unroll 16
            for (int kq = 0; kq < HID / 4; ++kq) {
                ulonglong2 r2 = rp[kq];
                ulonglong2 a  = wh[kq * DPC];
                FMA2(ah0, a.x, r2.x); FMA2(ah1, a.y, r2.y);
            }
            float2 h0 = unpack2(ah0), h1 = unpack2(ah1);
            // recompute z-gate (cheap vs keeping extra live regs): sigmoid of phase-1 preact
            unsigned long long az0 = 0ull, az1 = 0ull;
            const ulonglong2* wz = reinterpret_cast<const ulonglong2*>(&s->Wq[0][0][d]);
            // h vector unchanged during phase 2 (hq updated only after this sync) — reuse it
            const ulonglong2* hp = reinterpret_cast<const ulonglong2*>(&s->hq[b][0]);
            #pragma unroll 16
            for (int kq = 0; kq < HID / 4; ++kq) {
                ulonglong2 h2 = hp[kq];
                ulonglong2 a  = wz[kq * DPC];
                FMA2(az0, a.x, h2.x); FMA2(az1, a.y, h2.y);
            }
            float2 z0 = unpack2(az0), z1 = unpack2(az1);
            float xz = Wxz[xv * HID + dim];
            float zvv = 1.f / (1.f + expf(-(((z0.x + z0.y) + (z1.x + z1.y)) + xz + bzv)));

            float htl  = tanhf(((h0.x + h0.y) + (h1.x + h1.y)) + xh + bhv);
            float hnew = zvv * hold + (1.f - zvv) * htl;
            #pragma unroll
            for (int rr = 0; rr < CLUSTER; ++rr) st_cluster_f32(h_addr, rr, hnew);

            int row = t * BATCH + bg;
            __nv_bfloat16 hb = __float2bfloat16(hnew);
            g_Ahi[row * HID + dim] = hb;
            g_Alo[row * HID + dim] = __float2bfloat16(hnew - __bfloat162float(hb));
            if (t == STEPS - 1) outF[bg * HID + dim] = hnew;
        }
        CLUSTER_SYNC();
        if (tid == 0) st_rel(&g_prog[blockIdx.x], (unsigned)(t + 1));
    }
}

// ================= GEMM body (round-3 logic, smem from dynamic buffer) =================
#define CP16(dst, src, sz) \
    asm volatile("cp.async.cg.shared.global [%0], [%1], 16, %2;" :: "r"(dst), "l"(src), "r"(sz))
#define LDSM4(r, addr) \
    asm volatile("ldmatrix.sync.aligned.m8n8.x4.shared.b16 {%0,%1,%2,%3}, [%4];" \
        : "=r"((r)[0]), "=r"((r)[1]), "=r"((r)[2]), "=r"((r)[3]) : "r"(addr))
#define LDSMT2(r, addr) \
    asm volatile("ldmatrix.sync.aligned.m8n8.x2.trans.shared.b16 {%0,%1}, [%2];" \
        : "=r"((r)[0]), "=r"((r)[1]) : "r"(addr))
#define MMA16816(d, a, b) \
    asm volatile("mma.sync.aligned.m16n8k16.row.col.f32.bf16.bf16.f32 " \
        "{%0,%1,%2,%3}, {%4,%5,%6,%7}, {%8,%9}, {%0,%1,%2,%3};" \
        : "+f"((d)[0]), "+f"((d)[1]), "+f"((d)[2]), "+f"((d)[3]) \
        : "r"((a)[0]), "r"((a)[1]), "r"((a)[2]), "r"((a)[3]), "r"((b)[0]), "r"((b)[1]))

__device__ void gemm_body(int g, const float* __restrict__ bias, float* __restrict__ C)
{
    GSmem* gs = reinterpret_cast<GSmem*>(dyn_smem);
    const int tid  = threadIdx.x;
    const int lane = tid & 31;
    const int warp = tid >> 5;
    const int wm   = (warp >> 2) * 64;
    const int wn   = (warp & 3) * 32;
    const int mtile = g / NTN;
    const int ntile = g % NTN;
    const int m0   = mtile * GBM;
    const int n0   = ntile * GBN;

    // ---- band wait: all 64 recurrence CTAs past step 4*mtile+3 ----
    const unsigned need = (unsigned)(mtile * 4 + 4);
    if (tid < NREC) {
        while (ld_acq(&g_prog[tid]) < need) { }
    }
    __syncthreads();

    float acc[4][4][4];
    #pragma unroll
    for (int i = 0; i < 4; ++i)
        #pragma unroll
        for (int j = 0; j < 4; ++j)
            #pragma unroll
            for (int q = 0; q < 4; ++q) acc[i][j][q] = 0.f;

    auto load_stage = [&](int st, int k0) {
        #pragma unroll
        for (int i = 0; i < 2; ++i) {
            int idx = tid + (i << 8);
            int sel = idx >> 8;
            int r   = idx & 255;
            int m   = r >> 1;
            int ku  = r & 1;
            const __nv_bfloat16* gp = (sel ? g_Alo : g_Ahi) + (size_t)(m0 + m) * HID + k0 + ku * 8;
            uint32_t dd = sptr(sel ? gs->Al[st] : gs->Ah[st]) + m * 32 + ((ku ^ ((m >> 2) & 1)) << 4);
            CP16(dd, gp, 16);
        }
        #pragma unroll
        for (int i = 0; i < 2; ++i) {
            int idx = tid + (i << 8);
            int sel = idx >> 8;
            int r   = idx & 255;
            int k   = r >> 4;
            int nu  = r & 15;
            int col = n0 + nu * 8;
            const __nv_bfloat16* gp = (sel ? g_Blo : g_Bhi) + (size_t)(k0 + k) * VOCAB + col;
            uint32_t dd = sptr(sel ? gs->Bl[st] : gs->Bh[st]) + k * 256 + ((nu ^ (k & 7)) << 4);
            int sz = (col + 8 <= VOCAB) ? 16 : 0;
            CP16(dd, gp, sz);
        }
    };

    load_stage(0, 0);
    asm volatile("cp.async.commit_group;");

    const int lrow = lane & 15;
    const int lkb  = (lane >> 4) & 1;

    #pragma unroll 1
    for (int c = 0; c < GNC; ++c) {
        if (c + 1 < GNC) load_stage((c + 1) & 1, (c + 1) * GBK);
        asm volatile("cp.async.commit_group;");
        asm volatile("cp.async.wait_group 1;");
        __syncthreads();

        const int st = c & 1;
        uint32_t ah[4][4], al[4][4], bh[4][2], bl[4][2];
        #pragma unroll
        for (int mt = 0; mt < 4; ++mt) {
            int m = wm + mt * 16 + lrow;
            uint32_t off = m * 32 + ((lkb ^ ((m >> 2) & 1)) << 4);
            LDSM4(ah[mt], sptr(gs->Ah[st]) + off);
            LDSM4(al[mt], sptr(gs->Al[st]) + off);
        }
        #pragma unroll
        for (int nt = 0; nt < 4; ++nt) {
            int k = lrow;
            int n = wn + nt * 8;
            uint32_t off = k * 256 + (((n >> 3) ^ (k & 7)) << 4);
            LDSMT2(bh[nt], sptr(gs->Bh[st]) + off);
            LDSMT2(bl[nt], sptr(gs->Bl[st]) + off);
        }
        #pragma unroll
        for (int mt = 0; mt < 4; ++mt)
            #pragma unroll
            for (int nt = 0; nt < 4; ++nt) {
                MMA16816(acc[mt][nt], ah[mt], bh[nt]);
                MMA16816(acc[mt][nt], ah[mt], bl[nt]);
                MMA16816(acc[mt][nt], al[mt], bh[nt]);
            }
        __syncthreads();
    }

    #pragma unroll
    for (int nt = 0; nt < 4; ++nt) {
        int cbase = n0 + wn + nt * 8 + 2 * (lane & 3);
        float2 bv = make_float2(0.f, 0.f);
        if (cbase + 1 < VOCAB) bv = *reinterpret_cast<const float2*>(bias + cbase);
        #pragma unroll
        for (int mt = 0; mt < 4; ++mt) {
            int r0 = m0 + wm + mt * 16 + (lane >> 2);
            if (cbase + 1 < VOCAB) {
                float2 v0 = make_float2(acc[mt][nt][0] + bv.x, acc[mt][nt][1] + bv.y);
                float2 v1 = make_float2(acc[mt][nt][2] + bv.x, acc[mt][nt][3] + bv.y);
                *reinterpret_cast<float2*>(C + (size_t)r0 * VOCAB + cbase) = v0;
                *reinterpret_cast<float2*>(C + (size_t)(r0 + 8) * VOCAB + cbase) = v1;
            }
        }
    }
}

// ================= fused kernel =================
__global__ __launch_bounds__(FTH, 1) __cluster_dims__(CLUSTER, 1, 1)
void fused_kernel(const int* __restrict__ X, const float* __restrict__ H0,
                  const float* __restrict__ Wxz, const float* __restrict__ Whz, const float* __restrict__ bz,
                  const float* __restrict__ Wxr, const float* __restrict__ Whr, const float* __restrict__ br,
                  const float* __restrict__ Wxh, const float* __restrict__ Whh, const float* __restrict__ bh,
                  const float* __restrict__ bq, float* __restrict__ C, float* __restrict__ outF)
{
    if (blockIdx.x < NREC) {
        rnn_body(X, H0, Wxz, Whz, bz, Wxr, Whr, br, Wxh, Whh, bh, outF);
    } else {
        gemm_body((int)blockIdx.x - NREC, bq, C);
    }
}

// ================= launch =================
extern "C" void kernel_launch(void* const* d_in, const int* in_sizes, int n_in,
                              void* d_out, int out_size) {
    const int*   X   = (const int*)  d_in[0];
    const float* H0  = (const float*)d_in[1];
    const float* Wxz = (const float*)d_in[2];
    const float* Whz = (const float*)d_in[3];
    const float* bz  = (const float*)d_in[4];
    const float* Wxr = (const float*)d_in[5];
    const float* Whr = (const float*)d_in[6];
    const float* br  = (const float*)d_in[7];
    const float* Wxh = (const float*)d_in[8];
    const float* Whh = (const float*)d_in[9];
    const float* bh  = (const float*)d_in[10];
    const float* Whq = (const float*)d_in[11];
    const float* bq  = (const float*)d_in[12];

    float* out  = (float*)d_out;
    float* outF = out + (out_size - BATCH * HID);

    static bool attr_set = false;
    if (!attr_set) {
        cudaFuncSetAttribute(fused_kernel, cudaFuncAttributeMaxDynamicSharedMemorySize,
                             (int)sizeof(RSmem));
        attr_set = true;
    }

    prog_reset_kernel<<<1, 64>>>();
    convB_kernel<<<(HID * VOCAB + 255) / 256, 256>>>(Whq);
    fused_kernel<<<NREC + NTM * NTN, FTH, sizeof(RSmem)>>>(
        X, H0, Wxz, Whz, bz, Wxr, Whr, br, Wxh, Whh, bh, bq, out, outF);
}

// round 10
// speedup vs baseline: 2.2886x; 1.3494x over previous
#include <cuda_runtime.h>
#include <cuda_bf16.h>
#include <cstdint>

#define BATCH 32
#define HID   256
#define VOCAB 10000
#define STEPS 256

// ---------------- config ----------------
#define CLUSTER 4
#define BPC     2
#define DPC     64
#define NREC    64                 // recurrence CTAs (bids 0..63, wave 1)
#define FTH     256                // threads per CTA (fused kernel)

#define GBM 128
#define GBN 128
#define GBK 16
#define GNC (HID / GBK)
#define NTN ((VOCAB + GBN - 1) / GBN)   // 79 N tiles
#define NTM ((STEPS * BATCH) / GBM)     // 64 M tiles

// ---------------- scratch (device globals: allocation-free) ----------------
__device__ __nv_bfloat16 g_Ahi[STEPS * BATCH * HID];
__device__ __nv_bfloat16 g_Alo[STEPS * BATCH * HID];
__device__ __nv_bfloat16 g_Bhi[HID * VOCAB];
__device__ __nv_bfloat16 g_Blo[HID * VOCAB];
__device__ unsigned g_prog[NREC];   // per-recurrence-CTA step progress (t+1)

__global__ void prog_reset_kernel() {
    if (threadIdx.x < NREC) g_prog[threadIdx.x] = 0u;
}

__global__ void convB_kernel(const float* __restrict__ W) {
    int i = blockIdx.x * 256 + threadIdx.x;
    if (i < HID * VOCAB) {
        float v = W[i];
        __nv_bfloat16 h = __float2bfloat16(v);
        g_Bhi[i] = h;
        g_Blo[i] = __float2bfloat16(v - __bfloat162float(h));
    }
}

__device__ __forceinline__ uint32_t sptr(const void* p) {
    return (uint32_t)__cvta_generic_to_shared(p);
}
__device__ __forceinline__ unsigned ld_acq(const unsigned* p) {
    unsigned v;
    asm volatile("ld.acquire.gpu.global.u32 %0, [%1];" : "=r"(v) : "l"(p) : "memory");
    return v;
}
__device__ __forceinline__ void st_rel(unsigned* p, unsigned v) {
    asm volatile("st.release.gpu.global.u32 [%0], %1;" :: "l"(p), "r"(v) : "memory");
}

#define FMA2(acc, a, b) \
    asm("fma.rn.f32x2 %0, %1, %2, %0;" : "+l"(acc) : "l"(a), "l"(b))

__device__ __forceinline__ float2 unpack2(unsigned long long v) {
    float2 f;
    asm("mov.b64 {%0, %1}, %2;" : "=f"(f.x), "=f"(f.y) : "l"(v));
    return f;
}

__device__ __forceinline__ void st_cluster_f32(uint32_t laddr, int rank, float v) {
    uint32_t ra;
    asm("mapa.shared::cluster.u32 %0, %1, %2;" : "=r"(ra) : "r"(laddr), "r"(rank));
    asm volatile("st.shared::cluster.f32 [%0], %1;" :: "r"(ra), "f"(v) : "memory");
}

#define CLUSTER_SYNC() do { \
    asm volatile("barrier.cluster.arrive.aligned;" ::: "memory"); \
    asm volatile("barrier.cluster.wait.aligned;"   ::: "memory"); \
} while (0)

// ---------------- smem overlays (one dynamic buffer) ----------------
struct RSmem {                           // recurrence CTAs (R6-exact layout)
    float4 Wq[3][HID / 4][DPC];          // 196608 B
    float4 hq[BPC][HID / 4];
    float4 rhq[BPC][HID / 4];
};
struct GSmem {                           // GEMM CTAs (32 KB region of same buffer)
    __nv_bfloat16 Ah[2][GBM * GBK];
    __nv_bfloat16 Al[2][GBM * GBK];
    __nv_bfloat16 Bh[2][GBK * GBN];
    __nv_bfloat16 Bl[2][GBK * GBN];
};

extern __shared__ __align__(16) char dyn_smem[];

// ================= recurrence body (R6-exact phases, tid<128 active) =================
__device__ void rnn_body(const int* __restrict__ X, const float* __restrict__ H0,
                         const float* __restrict__ Wxz, const float* __restrict__ Whz, const float* __restrict__ bz,
                         const float* __restrict__ Wxr, const float* __restrict__ Whr, const float* __restrict__ br,
                         const float* __restrict__ Wxh, const float* __restrict__ Whh, const float* __restrict__ bh,
                         float* __restrict__ outF)
{
    RSmem* s = reinterpret_cast<RSmem*>(dyn_smem);
    const int tid    = threadIdx.x;
    const bool active = tid < 128;
    const int rank = (int)(blockIdx.x & (CLUSTER - 1));
    const int cid  = (int)(blockIdx.x >> 2);
    const int dim0 = rank * DPC;
    const int b    = tid & 1;
    const int d    = active ? (tid >> 1) : 0;
    const int bg   = cid * BPC + b;
    const int dim  = dim0 + d;

    // one-time weight slice load (all 256 threads help)
    for (int i = tid; i < 3 * (HID / 4) * DPC; i += FTH) {
        int g  = i / ((HID / 4) * DPC);
        int r  = i % ((HID / 4) * DPC);
        int kq = r / DPC;
        int dd = r % DPC;
        const float* W = (g == 0) ? Whz : ((g == 1) ? Whr : Whh);
        float4 v;
        v.x = W[(kq * 4 + 0) * HID + dim0 + dd];
        v.y = W[(kq * 4 + 1) * HID + dim0 + dd];
        v.z = W[(kq * 4 + 2) * HID + dim0 + dd];
        v.w = W[(kq * 4 + 3) * HID + dim0 + dd];
        s->Wq[g][kq][dd] = v;
    }
    if (tid < BPC * (HID / 4)) {
        int bb = tid >> 6;
        int kq = tid & 63;
        s->hq[bb][kq] = *reinterpret_cast<const float4*>(&H0[(cid * BPC + bb) * HID + kq * 4]);
    }
    const float bzv = bz[dim];
    const float brv = br[dim];
    const float bhv = bh[dim];
    __syncthreads();
    CLUSTER_SYNC();

    const uint32_t rh_addr = sptr(&reinterpret_cast<float*>(s->rhq)[b * HID + dim]);
    const uint32_t h_addr  = sptr(&reinterpret_cast<float*>(s->hq)[b * HID + dim]);

    #pragma unroll 1
    for (int t = 0; t < STEPS; ++t) {
        float zv = 0.f, hold = 0.f, xh = 0.f;   // carried in registers across sync

        if (active) {
            int   xv = X[bg * STEPS + t];
            float xz = Wxz[xv * HID + dim];
            float xr = Wxr[xv * HID + dim];
            xh   = Wxh[xv * HID + dim];          // prefetched; LDG overlaps phase-1 math
            hold = reinterpret_cast<const float*>(s->hq)[b * HID + dim];

            unsigned long long az0 = 0ull, az1 = 0ull, ar0 = 0ull, ar1 = 0ull;
            const ulonglong2* wz = reinterpret_cast<const ulonglong2*>(&s->Wq[0][0][d]);
            const ulonglong2* wr = reinterpret_cast<const ulonglong2*>(&s->Wq[1][0][d]);
            const ulonglong2* hp = reinterpret_cast<const ulonglong2*>(&s->hq[b][0]);
            #pragma unroll 16
            for (int kq = 0; kq < HID / 4; ++kq) {
                ulonglong2 h2 = hp[kq];
                ulonglong2 a  = wz[kq * DPC];
                ulonglong2 c  = wr[kq * DPC];
                FMA2(az0, a.x, h2.x); FMA2(az1, a.y, h2.y);
                FMA2(ar0, c.x, h2.x); FMA2(ar1, c.y, h2.y);
            }
            float2 z0 = unpack2(az0), z1 = unpack2(az1);
            float2 r0 = unpack2(ar0), r1 = unpack2(ar1);
            zv = 1.f / (1.f + expf(-(((z0.x + z0.y) + (z1.x + z1.y)) + xz + bzv)));
            float rv = 1.f / (1.f + expf(-(((r0.x + r0.y) + (r1.x + r1.y)) + xr + brv)));
            float rh = rv * hold;
            #pragma unroll
            for (int rr = 0; rr < CLUSTER; ++rr) st_cluster_f32(rh_addr, rr, rh);
        }
        CLUSTER_SYNC();

        if (active) {
            unsigned long long ah0 = 0ull, ah1 = 0ull;
            const ulonglong2* wh = reinterpret_cast<const ulonglong2*>(&s->Wq[2][0][d]);
            const ulonglong2* rp = reinterpret_cast<const ulonglong2*>(&s->rhq[b][0]);
            #pragma unroll 16
            for (int kq = 0; kq < HID / 4; ++kq) {
                ulonglong2 r2 = rp[kq];
                ulonglong2 a  = wh[kq * DPC];
                FMA2(ah0, a.x, r2.x); FMA2(ah1, a.y, r2.y);
            }
            float2 h0 = unpack2(ah0), h1 = unpack2(ah1);
            float htl  = tanhf(((h0.x + h0.y) + (h1.x + h1.y)) + xh + bhv);
            float hnew = zv * hold + (1.f - zv) * htl;
            #pragma unroll
            for (int rr = 0; rr < CLUSTER; ++rr) st_cluster_f32(h_addr, rr, hnew);

            int row = t * BATCH + bg;
            __nv_bfloat16 hb = __float2bfloat16(hnew);
            g_Ahi[row * HID + dim] = hb;
            g_Alo[row * HID + dim] = __float2bfloat16(hnew - __bfloat162float(hb));
            if (t == STEPS - 1) outF[bg * HID + dim] = hnew;
        }
        CLUSTER_SYNC();
        if (tid == 0) st_rel(&g_prog[blockIdx.x], (unsigned)(t + 1));
    }
}

// ================= GEMM body (round-3 logic, smem from dynamic buffer) =================
#define CP16(dst, src, sz) \
    asm volatile("cp.async.cg.shared.global [%0], [%1], 16, %2;" :: "r"(dst), "l"(src), "r"(sz))
#define LDSM4(r, addr) \
    asm volatile("ldmatrix.sync.aligned.m8n8.x4.shared.b16 {%0,%1,%2,%3}, [%4];" \
        : "=r"((r)[0]), "=r"((r)[1]), "=r"((r)[2]), "=r"((r)[3]) : "r"(addr))
#define LDSMT2(r, addr) \
    asm volatile("ldmatrix.sync.aligned.m8n8.x2.trans.shared.b16 {%0,%1}, [%2];" \
        : "=r"((r)[0]), "=r"((r)[1]) : "r"(addr))
#define MMA16816(d, a, b) \
    asm volatile("mma.sync.aligned.m16n8k16.row.col.f32.bf16.bf16.f32 " \
        "{%0,%1,%2,%3}, {%4,%5,%6,%7}, {%8,%9}, {%0,%1,%2,%3};" \
        : "+f"((d)[0]), "+f"((d)[1]), "+f"((d)[2]), "+f"((d)[3]) \
        : "r"((a)[0]), "r"((a)[1]), "r"((a)[2]), "r"((a)[3]), "r"((b)[0]), "r"((b)[1]))

__device__ void gemm_body(int g, const float* __restrict__ bias, float* __restrict__ C)
{
    GSmem* gs = reinterpret_cast<GSmem*>(dyn_smem);
    const int tid  = threadIdx.x;
    const int lane = tid & 31;
    const int warp = tid >> 5;
    const int wm   = (warp >> 2) * 64;
    const int wn   = (warp & 3) * 32;
    const int mtile = g / NTN;
    const int ntile = g % NTN;
    const int m0   = mtile * GBM;
    const int n0   = ntile * GBN;

    // ---- band wait: all 64 recurrence CTAs past step 4*mtile+3 ----
    // sleep-backoff poll: don't hammer L2 while the recurrence is running
    const unsigned need = (unsigned)(mtile * 4 + 4);
    if (tid < NREC) {
        while (ld_acq(&g_prog[tid]) < need) __nanosleep(256);
    }
    __syncthreads();

    float acc[4][4][4];
    #pragma unroll
    for (int i = 0; i < 4; ++i)
        #pragma unroll
        for (int j = 0; j < 4; ++j)
            #pragma unroll
            for (int q = 0; q < 4; ++q) acc[i][j][q] = 0.f;

    auto load_stage = [&](int st, int k0) {
        #pragma unroll
        for (int i = 0; i < 2; ++i) {
            int idx = tid + (i << 8);
            int sel = idx >> 8;
            int r   = idx & 255;
            int m   = r >> 1;
            int ku  = r & 1;
            const __nv_bfloat16* gp = (sel ? g_Alo : g_Ahi) + (size_t)(m0 + m) * HID + k0 + ku * 8;
            uint32_t dd = sptr(sel ? gs->Al[st] : gs->Ah[st]) + m * 32 + ((ku ^ ((m >> 2) & 1)) << 4);
            CP16(dd, gp, 16);
        }
        #pragma unroll
        for (int i = 0; i < 2; ++i) {
            int idx = tid + (i << 8);
            int sel = idx >> 8;
            int r   = idx & 255;
            int k   = r >> 4;
            int nu  = r & 15;
            int col = n0 + nu * 8;
            const __nv_bfloat16* gp = (sel ? g_Blo : g_Bhi) + (size_t)(k0 + k) * VOCAB + col;
            uint32_t dd = sptr(sel ? gs->Bl[st] : gs->Bh[st]) + k * 256 + ((nu ^ (k & 7)) << 4);
            int sz = (col + 8 <= VOCAB) ? 16 : 0;
            CP16(dd, gp, sz);
        }
    };

    load_stage(0, 0);
    asm volatile("cp.async.commit_group;");

    const int lrow = lane & 15;
    const int lkb  = (lane >> 4) & 1;

    #pragma unroll 1
    for (int c = 0; c < GNC; ++c) {
        if (c + 1 < GNC) load_stage((c + 1) & 1, (c + 1) * GBK);
        asm volatile("cp.async.commit_group;");
        asm volatile("cp.async.wait_group 1;");
        __syncthreads();

        const int st = c & 1;
        uint32_t ah[4][4], al[4][4], bh[4][2], bl[4][2];
        #pragma unroll
        for (int mt = 0; mt < 4; ++mt) {
            int m = wm + mt * 16 + lrow;
            uint32_t off = m * 32 + ((lkb ^ ((m >> 2) & 1)) << 4);
            LDSM4(ah[mt], sptr(gs->Ah[st]) + off);
            LDSM4(al[mt], sptr(gs->Al[st]) + off);
        }
        #pragma unroll
        for (int nt = 0; nt < 4; ++nt) {
            int k = lrow;
            int n = wn + nt * 8;
            uint32_t off = k * 256 + (((n >> 3) ^ (k & 7)) << 4);
            LDSMT2(bh[nt], sptr(gs->Bh[st]) + off);
            LDSMT2(bl[nt], sptr(gs->Bl[st]) + off);
        }
        #pragma unroll
        for (int mt = 0; mt < 4; ++mt)
            #pragma unroll
            for (int nt = 0; nt < 4; ++nt) {
                MMA16816(acc[mt][nt], ah[mt], bh[nt]);
                MMA16816(acc[mt][nt], ah[mt], bl[nt]);
                MMA16816(acc[mt][nt], al[mt], bh[nt]);
            }
        __syncthreads();
    }

    #pragma unroll
    for (int nt = 0; nt < 4; ++nt) {
        int cbase = n0 + wn + nt * 8 + 2 * (lane & 3);
        float2 bv = make_float2(0.f, 0.f);
        if (cbase + 1 < VOCAB) bv = *reinterpret_cast<const float2*>(bias + cbase);
        #pragma unroll
        for (int mt = 0; mt < 4; ++mt) {
            int r0 = m0 + wm + mt * 16 + (lane >> 2);
            if (cbase + 1 < VOCAB) {
                float2 v0 = make_float2(acc[mt][nt][0] + bv.x, acc[mt][nt][1] + bv.y);
                float2 v1 = make_float2(acc[mt][nt][2] + bv.x, acc[mt][nt][3] + bv.y);
                *reinterpret_cast<float2*>(C + (size_t)r0 * VOCAB + cbase) = v0;
                *reinterpret_cast<float2*>(C + (size_t)(r0 + 8) * VOCAB + cbase) = v1;
            }
        }
    }
}

// ================= fused kernel =================
__global__ __launch_bounds__(FTH, 1) __cluster_dims__(CLUSTER, 1, 1)
void fused_kernel(const int* __restrict__ X, const float* __restrict__ H0,
                  const float* __restrict__ Wxz, const float* __restrict__ Whz, const float* __restrict__ bz,
                  const float* __restrict__ Wxr, const float* __restrict__ Whr, const float* __restrict__ br,
                  const float* __restrict__ Wxh, const float* __restrict__ Whh, const float* __restrict__ bh,
                  const float* __restrict__ bq, float* __restrict__ C, float* __restrict__ outF)
{
    if (blockIdx.x < NREC) {
        rnn_body(X, H0, Wxz, Whz, bz, Wxr, Whr, br, Wxh, Whh, bh, outF);
    } else {
        gemm_body((int)blockIdx.x - NREC, bq, C);
    }
}

// ================= launch =================
extern "C" void kernel_launch(void* const* d_in, const int* in_sizes, int n_in,
                              void* d_out, int out_size) {
    const int*   X   = (const int*)  d_in[0];
    const float* H0  = (const float*)d_in[1];
    const float* Wxz = (const float*)d_in[2];
    const float* Whz = (const float*)d_in[3];
    const float* bz  = (const float*)d_in[4];
    const float* Wxr = (const float*)d_in[5];
    const float* Whr = (const float*)d_in[6];
    const float* br  = (const float*)d_in[7];
    const float* Wxh = (const float*)d_in[8];
    const float* Whh = (const float*)d_in[9];
    const float* bh  = (const float*)d_in[10];
    const float* Whq = (const float*)d_in[11];
    const float* bq  = (const float*)d_in[12];

    float* out  = (float*)d_out;
    float* outF = out + (out_size - BATCH * HID);

    static bool attr_set = false;
    if (!attr_set) {
        cudaFuncSetAttribute(fused_kernel, cudaFuncAttributeMaxDynamicSharedMemorySize,
                             (int)sizeof(RSmem));
        attr_set = true;
    }

    prog_reset_kernel<<<1, 64>>>();
    convB_kernel<<<(HID * VOCAB + 255) / 256, 256>>>(Whq);
    fused_kernel<<<NREC + NTM * NTN, FTH, sizeof(RSmem)>>>(
        X, H0, Wxz, Whz, bz, Wxr, Whr, br, Wxh, Whh, bh, bq, out, outF);
}